// round 15
// baseline (speedup 1.0000x reference)
#include <cuda_runtime.h>
#include <cuda_fp16.h>

// ---------------------------------------------------------------------------
// GTBlock: out = x + sum_r GATv2_r(LN(x)) + MLP(LN(x))
// N=100000, E=640000, C=128, H=4 (DH=32), 3 relations.
// R15 = R11 (passing, 974.8us) + launch-graph overlap: mlp1 is fused with e1
// and mlp2 with e2 in single kernels (block-range dispatch, mlp blocks
// interleaved every 103rd block) so compute-bound GEMM warps and
// memory-bound edge warps co-reside. HFMA2 (R14, regressed) reverted.
// ---------------------------------------------------------------------------

#define Nn 100000
#define Ee 640000
#define Cc 128
#define Hh 4
#define CC (Cc*Cc)
#define NC (Nn*Cc)
#define NCH (Nn*64)          /* u32 per relation plane for fp16 rows */
#define MT 782               /* 128-row GEMM tiles */
#define ILV 103              /* interleave stride for fused phases */
#define GRID_FUSED 80786     /* ceil/checked: 785 mlp slots, 80001 edge blocks */

// -------------------- static scratch (no allocations allowed) --------------
__device__ __align__(16) float    g_x1 [NC];      // LN(x)
__device__ __align__(16) unsigned g_XLp[3*NCH];   // lin_l, packed fp16 pairs
__device__ __align__(16) unsigned g_XRp[3*NCH];   // lin_r, packed fp16 pairs
__device__ __align__(16) float    g_h  [NC];      // MLP hidden
__device__ __align__(16) float    g_mlp[NC];      // MLP out
__device__ __align__(16) float    g_gat[NC];      // GAT aggregation (atomic target)
__device__ __align__(16) float    g_p  [Ee*Hh];   // per-edge exp(logit)
__device__ __align__(16) float    g_den[Nn*12];   // softmax denominators [N][3][H]
__device__ int g_src[Ee];
__device__ int g_dst[Ee];
__device__ int g_et [Ee];
__device__ int g_is64;

// -------------------- by-value fp16 pack/unpack helpers --------------------
__device__ __forceinline__ unsigned hpack2(float a, float b) {
    unsigned lo = (unsigned)__half_as_ushort(__float2half_rn(a));
    unsigned hi = (unsigned)__half_as_ushort(__float2half_rn(b));
    return lo | (hi << 16);
}
__device__ __forceinline__ float hlo(unsigned u) {
    return __half2float(__ushort_as_half((unsigned short)(u & 0xFFFFu)));
}
__device__ __forceinline__ float hhi(unsigned u) {
    return __half2float(__ushort_as_half((unsigned short)(u >> 16)));
}

// -------------------- f32x2 packed-FMA helpers (R11, passed) ---------------
__device__ __forceinline__ unsigned long long pk64(float lo, float hi) {
    unsigned long long r;
    asm("mov.b64 %0, {%1, %2};" : "=l"(r)
        : "r"(__float_as_uint(lo)), "r"(__float_as_uint(hi)));
    return r;
}
__device__ __forceinline__ unsigned long long ffma2(unsigned long long a,
                                                    unsigned long long b,
                                                    unsigned long long c) {
    unsigned long long d;
    asm("fma.rn.f32x2 %0, %1, %2, %3;" : "=l"(d) : "l"(a), "l"(b), "l"(c));
    return d;
}
__device__ __forceinline__ float lo32(unsigned long long v) {
    return __uint_as_float((unsigned)(v & 0xFFFFFFFFull));
}
__device__ __forceinline__ float hi32(unsigned long long v) {
    return __uint_as_float((unsigned)(v >> 32));
}

// -------------------- int64-vs-int32 edge_index detection ------------------
__global__ void detect_kernel(const void* ei) {
    const long long* p = (const long long*)ei;
    int ok = 1;
    for (int i = 0; i < 8; i++) {
        long long v = p[i];
        if (v < 0 || v >= (long long)Nn) ok = 0;
    }
    g_is64 = ok;
}

__global__ void convert_kernel(const void* ei, const int* __restrict__ ea) {
    int i = blockIdx.x * blockDim.x + threadIdx.x;
    if (i >= Ee) return;
    int s, d;
    if (g_is64) {
        const long long* p = (const long long*)ei;
        s = (int)p[i];
        d = (int)p[Ee + i];
    } else {
        const int* p = (const int*)ei;
        s = p[i];
        d = p[Ee + i];
    }
    g_src[i] = s;
    g_dst[i] = d;
    g_et[i]  = ea[i] + 1;   // {-1,0,1} -> {0,1,2}
}

// -------------------- zero scratch -----------------------------------------
__global__ void zero_kernel() {
    int i = blockIdx.x * blockDim.x + threadIdx.x;
    if (i < NC)     g_gat[i] = 0.0f;
    if (i < Nn*12)  g_den[i] = 0.0f;
}

// -------------------- LayerNorm (1 warp per row) ---------------------------
__global__ void ln_kernel(const float* __restrict__ x,
                          const float* __restrict__ w,
                          const float* __restrict__ b) {
    int warp = (blockIdx.x * blockDim.x + threadIdx.x) >> 5;
    int lane = threadIdx.x & 31;
    if (warp >= Nn) return;
    const float4* xr = (const float4*)(x + (size_t)warp * Cc);
    float4 v = xr[lane];
    float s = v.x + v.y + v.z + v.w;
    #pragma unroll
    for (int o = 16; o > 0; o >>= 1) s += __shfl_xor_sync(0xffffffffu, s, o);
    float mu = s * (1.0f / Cc);
    float dx = v.x - mu, dy = v.y - mu, dz = v.z - mu, dw = v.w - mu;
    float q = dx*dx + dy*dy + dz*dz + dw*dw;
    #pragma unroll
    for (int o = 16; o > 0; o >>= 1) q += __shfl_xor_sync(0xffffffffu, q, o);
    float var = q * (1.0f / Cc);
    float r = rsqrtf(var + 1e-5f);
    r = r * (1.5f - 0.5f * (var + 1e-5f) * r * r);   // Newton refine
    float4 wv = ((const float4*)w)[lane];
    float4 bv = ((const float4*)b)[lane];
    float4 o4;
    o4.x = dx * r * wv.x + bv.x;
    o4.y = dy * r * wv.y + bv.y;
    o4.z = dz * r * wv.z + bv.z;
    o4.w = dw * r * wv.w + bv.w;
    ((float4*)(g_x1 + (size_t)warp * Cc))[lane] = o4;
}

// -------------------- fp32 SGEMM tile (R11, passed) ------------------------
__device__ __forceinline__ void gemm_tile(const float* __restrict__ A,
                                          const float* __restrict__ W,
                                          const float* __restrict__ bias,
                                          float* __restrict__ Y,
                                          int M, int act, int bm) {
    __shared__ float As[16][132];
    __shared__ float Bs[16][132];
    int tid = threadIdx.x;
    int ty = tid >> 4, tx = tid & 15;

    unsigned long long acc2[8][4];
    #pragma unroll
    for (int i = 0; i < 8; i++)
        #pragma unroll
        for (int j = 0; j < 4; j++) acc2[i][j] = 0ull;

    for (int k0 = 0; k0 < 128; k0 += 16) {
        #pragma unroll
        for (int u = 0; u < 2; u++) {
            int q = tid + u * 256;
            int row = q >> 2, c4 = q & 3;
            int grow = bm + row;
            float4 a = (grow < M)
                ? ((const float4*)(A + (size_t)grow * 128 + k0))[c4]
                : make_float4(0.f, 0.f, 0.f, 0.f);
            As[c4*4+0][row] = a.x;
            As[c4*4+1][row] = a.y;
            As[c4*4+2][row] = a.z;
            As[c4*4+3][row] = a.w;
        }
        #pragma unroll
        for (int u = 0; u < 2; u++) {
            int q = tid + u * 256;
            int row = q >> 5, c4 = q & 31;
            float4 bvec = ((const float4*)(W + (size_t)(k0 + row) * 128))[c4];
            *(float4*)&Bs[row][c4 * 4] = bvec;
        }
        __syncthreads();
        #pragma unroll
        for (int k = 0; k < 16; k++) {
            float a[8], bb[8];
            *(float4*)&a[0]  = *(const float4*)&As[k][ty * 8];
            *(float4*)&a[4]  = *(const float4*)&As[k][ty * 8 + 4];
            *(float4*)&bb[0] = *(const float4*)&Bs[k][tx * 8];
            *(float4*)&bb[4] = *(const float4*)&Bs[k][tx * 8 + 4];
            unsigned long long b0 = pk64(bb[0], bb[1]);
            unsigned long long b1 = pk64(bb[2], bb[3]);
            unsigned long long b2 = pk64(bb[4], bb[5]);
            unsigned long long b3 = pk64(bb[6], bb[7]);
            #pragma unroll
            for (int i = 0; i < 8; i++) {
                unsigned long long aa = pk64(a[i], a[i]);
                acc2[i][0] = ffma2(aa, b0, acc2[i][0]);
                acc2[i][1] = ffma2(aa, b1, acc2[i][1]);
                acc2[i][2] = ffma2(aa, b2, acc2[i][2]);
                acc2[i][3] = ffma2(aa, b3, acc2[i][3]);
            }
        }
        __syncthreads();
    }

    float bset[8];
    *(float4*)&bset[0] = *(const float4*)(bias + tx * 8);
    *(float4*)&bset[4] = *(const float4*)(bias + tx * 8 + 4);
    #pragma unroll
    for (int i = 0; i < 8; i++) {
        int grow = bm + ty * 8 + i;
        if (grow >= M) continue;
        float o[8];
        #pragma unroll
        for (int j = 0; j < 4; j++) {
            float v0 = lo32(acc2[i][j]) + bset[2*j];
            float v1 = hi32(acc2[i][j]) + bset[2*j + 1];
            if (act) {
                v0 = 0.5f * v0 * (1.0f + erff(v0 * 0.70710678118654752f));
                v1 = 0.5f * v1 * (1.0f + erff(v1 * 0.70710678118654752f));
            }
            o[2*j]     = v0;
            o[2*j + 1] = v1;
        }
        *(float4*)(Y + (size_t)grow * 128 + tx * 8)     = *(float4*)&o[0];
        *(float4*)(Y + (size_t)grow * 128 + tx * 8 + 4) = *(float4*)&o[4];
    }
}

// Same tile, epilogue packs to fp16 pairs (XL/XR planes).
__device__ __forceinline__ void gemm_tile_h(const float* __restrict__ A,
                                            const float* __restrict__ W,
                                            const float* __restrict__ bias,
                                            unsigned* __restrict__ Y16,
                                            int M, int bm) {
    __shared__ float As[16][132];
    __shared__ float Bs[16][132];
    int tid = threadIdx.x;
    int ty = tid >> 4, tx = tid & 15;

    unsigned long long acc2[8][4];
    #pragma unroll
    for (int i = 0; i < 8; i++)
        #pragma unroll
        for (int j = 0; j < 4; j++) acc2[i][j] = 0ull;

    for (int k0 = 0; k0 < 128; k0 += 16) {
        #pragma unroll
        for (int u = 0; u < 2; u++) {
            int q = tid + u * 256;
            int row = q >> 2, c4 = q & 3;
            int grow = bm + row;
            float4 a = (grow < M)
                ? ((const float4*)(A + (size_t)grow * 128 + k0))[c4]
                : make_float4(0.f, 0.f, 0.f, 0.f);
            As[c4*4+0][row] = a.x;
            As[c4*4+1][row] = a.y;
            As[c4*4+2][row] = a.z;
            As[c4*4+3][row] = a.w;
        }
        #pragma unroll
        for (int u = 0; u < 2; u++) {
            int q = tid + u * 256;
            int row = q >> 5, c4 = q & 31;
            float4 bvec = ((const float4*)(W + (size_t)(k0 + row) * 128))[c4];
            *(float4*)&Bs[row][c4 * 4] = bvec;
        }
        __syncthreads();
        #pragma unroll
        for (int k = 0; k < 16; k++) {
            float a[8], bb[8];
            *(float4*)&a[0]  = *(const float4*)&As[k][ty * 8];
            *(float4*)&a[4]  = *(const float4*)&As[k][ty * 8 + 4];
            *(float4*)&bb[0] = *(const float4*)&Bs[k][tx * 8];
            *(float4*)&bb[4] = *(const float4*)&Bs[k][tx * 8 + 4];
            unsigned long long b0 = pk64(bb[0], bb[1]);
            unsigned long long b1 = pk64(bb[2], bb[3]);
            unsigned long long b2 = pk64(bb[4], bb[5]);
            unsigned long long b3 = pk64(bb[6], bb[7]);
            #pragma unroll
            for (int i = 0; i < 8; i++) {
                unsigned long long aa = pk64(a[i], a[i]);
                acc2[i][0] = ffma2(aa, b0, acc2[i][0]);
                acc2[i][1] = ffma2(aa, b1, acc2[i][1]);
                acc2[i][2] = ffma2(aa, b2, acc2[i][2]);
                acc2[i][3] = ffma2(aa, b3, acc2[i][3]);
            }
        }
        __syncthreads();
    }

    float bset[8];
    *(float4*)&bset[0] = *(const float4*)(bias + tx * 8);
    *(float4*)&bset[4] = *(const float4*)(bias + tx * 8 + 4);
    #pragma unroll
    for (int i = 0; i < 8; i++) {
        int grow = bm + ty * 8 + i;
        if (grow >= M) continue;
        uint4 pk;
        pk.x = hpack2(lo32(acc2[i][0]) + bset[0], hi32(acc2[i][0]) + bset[1]);
        pk.y = hpack2(lo32(acc2[i][1]) + bset[2], hi32(acc2[i][1]) + bset[3]);
        pk.z = hpack2(lo32(acc2[i][2]) + bset[4], hi32(acc2[i][2]) + bset[5]);
        pk.w = hpack2(lo32(acc2[i][3]) + bset[6], hi32(acc2[i][3]) + bset[7]);
        ((uint4*)(Y16 + (size_t)grow * 64))[tx] = pk;
    }
}

// 6-way GEMM: XL[r] = x1@Wl[r]+bl[r],  XR[r] = x1@Wr[r]+br[r]  (fp16 planes)
__global__ void __launch_bounds__(256) gemm6_kernel(const float* __restrict__ Wl,
                                                    const float* __restrict__ bl,
                                                    const float* __restrict__ Wr,
                                                    const float* __restrict__ br) {
    int y = blockIdx.y;
    int r = (y < 3) ? y : y - 3;
    const float* W  = ((y < 3) ? Wl : Wr) + (size_t)r * CC;
    const float* bb = ((y < 3) ? bl : br) + (size_t)r * Cc;
    unsigned* Y = ((y < 3) ? g_XLp : g_XRp) + (size_t)r * NCH;
    gemm_tile_h(g_x1, W, bb, Y, Nn, blockIdx.x * 128);
}

// -------------------- edge-pass device bodies (R11, passed) ----------------
__device__ __forceinline__ void e1_body(int gw, int lane, const float* __restrict__ att) {
    int s = g_src[gw], d = g_dst[gw], t = g_et[gw];
    const uint2* xl = (const uint2*)(g_XLp + (size_t)t * NCH + (size_t)s * 64);
    const uint2* xr = (const uint2*)(g_XRp + (size_t)t * NCH + (size_t)d * 64);
    uint2 ua = xl[lane];
    uint2 ub = xr[lane];
    float z0 = hlo(ua.x) + hlo(ub.x);
    float z1 = hhi(ua.x) + hhi(ub.x);
    float z2 = hlo(ua.y) + hlo(ub.y);
    float z3 = hhi(ua.y) + hhi(ub.y);
    z0 = (z0 >= 0.f) ? z0 : 0.2f * z0;
    z1 = (z1 >= 0.f) ? z1 : 0.2f * z1;
    z2 = (z2 >= 0.f) ? z2 : 0.2f * z2;
    z3 = (z3 >= 0.f) ? z3 : 0.2f * z3;
    float4 av = ((const float4*)(att + (size_t)t * Cc))[lane];
    float e = z0 * av.x + z1 * av.y + z2 * av.z + z3 * av.w;
    e += __shfl_xor_sync(0xffffffffu, e, 1);
    e += __shfl_xor_sync(0xffffffffu, e, 2);
    e += __shfl_xor_sync(0xffffffffu, e, 4);     // 8-lane group = one head
    if ((lane & 7) == 0) {
        int h = lane >> 3;
        float p = expf(e);
        g_p[(size_t)gw * 4 + h] = p;
        atomicAdd(&g_den[(size_t)d * 12 + t * 4 + h], p);
    }
}

__device__ __forceinline__ void e2_body(int gw, int lane) {
    int s = g_src[gw], d = g_dst[gw], t = g_et[gw];
    int h = lane >> 3;
    float p   = g_p[(size_t)gw * 4 + h];
    float den = g_den[(size_t)d * 12 + t * 4 + h];
    float alpha = p / ((den > 0.f) ? den : 1.f);
    const uint2* xl = (const uint2*)(g_XLp + (size_t)t * NCH + (size_t)s * 64);
    uint2 ua = xl[lane];
    float a0 = hlo(ua.x), a1 = hhi(ua.x), a2 = hlo(ua.y), a3 = hhi(ua.y);
    float* dst = g_gat + (size_t)d * Cc + lane * 4;
    asm volatile("red.global.add.v4.f32 [%0], {%1, %2, %3, %4};"
                 :: "l"(dst), "f"(a0 * alpha), "f"(a1 * alpha),
                    "f"(a2 * alpha), "f"(a3 * alpha)
                 : "memory");
}

// -------------------- fused phase A: mlp1 (interleaved) + e1 ---------------
// Block bid with bid%ILV==0 and bid/ILV<MT runs a mlp1 tile; all other
// blocks run 8 e1 edge-warps. Interleaving keeps GEMM (compute) and edge
// (memory) warps co-resident on each SM.
__global__ void __launch_bounds__(256) fusedA_kernel(const float* __restrict__ mW1,
                                                     const float* __restrict__ mb1,
                                                     const float* __restrict__ att) {
    int bid = blockIdx.x;
    int q = bid / ILV, rr = bid - q * ILV;
    if (rr == 0) {
        if (q < MT)
            gemm_tile(g_x1, mW1, mb1, g_h, Nn, 1, q * 128);
        return;
    }
    int eb = bid - q - 1;                       // contiguous edge-block index
    int gw = eb * 8 + (threadIdx.x >> 5);
    if (gw >= Ee) return;
    e1_body(gw, threadIdx.x & 31, att);
}

// -------------------- fused phase B: mlp2 (interleaved) + e2 ---------------
__global__ void __launch_bounds__(256) fusedB_kernel(const float* __restrict__ mW2,
                                                     const float* __restrict__ mb2) {
    int bid = blockIdx.x;
    int q = bid / ILV, rr = bid - q * ILV;
    if (rr == 0) {
        if (q < MT)
            gemm_tile(g_h, mW2, mb2, g_mlp, Nn, 1, q * 128);
        return;
    }
    int eb = bid - q - 1;
    int gw = eb * 8 + (threadIdx.x >> 5);
    if (gw >= Ee) return;
    e2_body(gw, threadIdx.x & 31);
}

// -------------------- final residual ---------------------------------------
__global__ void final_kernel(const float* __restrict__ x,
                             const float* __restrict__ gbias,
                             float* __restrict__ out) {
    int i = blockIdx.x * blockDim.x + threadIdx.x;
    if (i >= NC) return;
    int c = i & 127;
    float gb = gbias[c] + gbias[128 + c] + gbias[256 + c];
    out[i] = x[i] + g_gat[i] + g_mlp[i] + gb;
}

// ---------------------------------------------------------------------------
extern "C" void kernel_launch(void* const* d_in, const int* in_sizes, int n_in,
                              void* d_out, int out_size) {
    const float* x    = (const float*)d_in[0];
    const void*  ei   = d_in[1];                  // int64 or int32, detected on-device
    const int*   ea   = (const int*)d_in[2];
    const float* ln_w = (const float*)d_in[3];
    const float* ln_b = (const float*)d_in[4];
    const float* Wl   = (const float*)d_in[5];
    const float* bl   = (const float*)d_in[6];
    const float* Wr   = (const float*)d_in[7];
    const float* br   = (const float*)d_in[8];
    const float* att  = (const float*)d_in[9];
    const float* gb   = (const float*)d_in[10];
    const float* mW1  = (const float*)d_in[11];
    const float* mb1  = (const float*)d_in[12];
    const float* mW2  = (const float*)d_in[13];
    const float* mb2  = (const float*)d_in[14];
    float* out = (float*)d_out;

    detect_kernel<<<1, 1>>>(ei);
    convert_kernel<<<(Ee + 255) / 256, 256>>>(ei, ea);
    zero_kernel<<<(NC + 255) / 256, 256>>>();
    ln_kernel<<<(Nn * 32 + 255) / 256, 256>>>(x, ln_w, ln_b);

    gemm6_kernel<<<dim3(MT, 6), 256>>>(Wl, bl, Wr, br);

    fusedA_kernel<<<GRID_FUSED, 256>>>(mW1, mb1, att);   // mlp1 || e1
    fusedB_kernel<<<GRID_FUSED, 256>>>(mW2, mb2);        // mlp2 || e2

    final_kernel<<<(NC + 255) / 256, 256>>>(x, gb, out);
}

// round 16
// speedup vs baseline: 1.7377x; 1.7377x over previous
#include <cuda_runtime.h>
#include <cuda_fp16.h>

// ---------------------------------------------------------------------------
// GTBlock: out = x + sum_r GATv2_r(LN(x)) + MLP(LN(x))
// N=100000, E=640000, C=128, H=4 (DH=32), 3 relations.
// R16 = R11 (passing, 974.8us) + graph fork/join stream overlap:
//   null stream : gemm6 -> e1 -> e2 -> (join) -> final
//   side stream : (fork after ln) -> mlp1 -> mlp2
// The FMA-bound MLP chain runs concurrently with gemm6 + the memory-bound
// edge passes. Kernels keep their own resource shapes (R15's block-level
// fusion poisoned edge-block occupancy and regressed 650us -> abandoned).
// ---------------------------------------------------------------------------

#define Nn 100000
#define Ee 640000
#define Cc 128
#define Hh 4
#define CC (Cc*Cc)
#define NC (Nn*Cc)
#define NCH (Nn*64)          /* u32 per relation plane for fp16 rows */

// -------------------- static scratch (no allocations allowed) --------------
__device__ __align__(16) float    g_x1 [NC];      // LN(x)
__device__ __align__(16) unsigned g_XLp[3*NCH];   // lin_l, packed fp16 pairs
__device__ __align__(16) unsigned g_XRp[3*NCH];   // lin_r, packed fp16 pairs
__device__ __align__(16) float    g_h  [NC];      // MLP hidden
__device__ __align__(16) float    g_mlp[NC];      // MLP out
__device__ __align__(16) float    g_gat[NC];      // GAT aggregation (atomic target)
__device__ __align__(16) float    g_p  [Ee*Hh];   // per-edge exp(logit)
__device__ __align__(16) float    g_den[Nn*12];   // softmax denominators [N][3][H]
__device__ int g_src[Ee];
__device__ int g_dst[Ee];
__device__ int g_et [Ee];
__device__ int g_is64;

// -------------------- by-value fp16 pack/unpack helpers --------------------
__device__ __forceinline__ unsigned hpack2(float a, float b) {
    unsigned lo = (unsigned)__half_as_ushort(__float2half_rn(a));
    unsigned hi = (unsigned)__half_as_ushort(__float2half_rn(b));
    return lo | (hi << 16);
}
__device__ __forceinline__ float hlo(unsigned u) {
    return __half2float(__ushort_as_half((unsigned short)(u & 0xFFFFu)));
}
__device__ __forceinline__ float hhi(unsigned u) {
    return __half2float(__ushort_as_half((unsigned short)(u >> 16)));
}

// -------------------- f32x2 packed-FMA helpers (R11, passed) ---------------
__device__ __forceinline__ unsigned long long pk64(float lo, float hi) {
    unsigned long long r;
    asm("mov.b64 %0, {%1, %2};" : "=l"(r)
        : "r"(__float_as_uint(lo)), "r"(__float_as_uint(hi)));
    return r;
}
__device__ __forceinline__ unsigned long long ffma2(unsigned long long a,
                                                    unsigned long long b,
                                                    unsigned long long c) {
    unsigned long long d;
    asm("fma.rn.f32x2 %0, %1, %2, %3;" : "=l"(d) : "l"(a), "l"(b), "l"(c));
    return d;
}
__device__ __forceinline__ float lo32(unsigned long long v) {
    return __uint_as_float((unsigned)(v & 0xFFFFFFFFull));
}
__device__ __forceinline__ float hi32(unsigned long long v) {
    return __uint_as_float((unsigned)(v >> 32));
}

// -------------------- int64-vs-int32 edge_index detection ------------------
__global__ void detect_kernel(const void* ei) {
    const long long* p = (const long long*)ei;
    int ok = 1;
    for (int i = 0; i < 8; i++) {
        long long v = p[i];
        if (v < 0 || v >= (long long)Nn) ok = 0;
    }
    g_is64 = ok;
}

__global__ void convert_kernel(const void* ei, const int* __restrict__ ea) {
    int i = blockIdx.x * blockDim.x + threadIdx.x;
    if (i >= Ee) return;
    int s, d;
    if (g_is64) {
        const long long* p = (const long long*)ei;
        s = (int)p[i];
        d = (int)p[Ee + i];
    } else {
        const int* p = (const int*)ei;
        s = p[i];
        d = p[Ee + i];
    }
    g_src[i] = s;
    g_dst[i] = d;
    g_et[i]  = ea[i] + 1;   // {-1,0,1} -> {0,1,2}
}

// -------------------- zero scratch -----------------------------------------
__global__ void zero_kernel() {
    int i = blockIdx.x * blockDim.x + threadIdx.x;
    if (i < NC)     g_gat[i] = 0.0f;
    if (i < Nn*12)  g_den[i] = 0.0f;
}

// -------------------- LayerNorm (1 warp per row) ---------------------------
__global__ void ln_kernel(const float* __restrict__ x,
                          const float* __restrict__ w,
                          const float* __restrict__ b) {
    int warp = (blockIdx.x * blockDim.x + threadIdx.x) >> 5;
    int lane = threadIdx.x & 31;
    if (warp >= Nn) return;
    const float4* xr = (const float4*)(x + (size_t)warp * Cc);
    float4 v = xr[lane];
    float s = v.x + v.y + v.z + v.w;
    #pragma unroll
    for (int o = 16; o > 0; o >>= 1) s += __shfl_xor_sync(0xffffffffu, s, o);
    float mu = s * (1.0f / Cc);
    float dx = v.x - mu, dy = v.y - mu, dz = v.z - mu, dw = v.w - mu;
    float q = dx*dx + dy*dy + dz*dz + dw*dw;
    #pragma unroll
    for (int o = 16; o > 0; o >>= 1) q += __shfl_xor_sync(0xffffffffu, q, o);
    float var = q * (1.0f / Cc);
    float r = rsqrtf(var + 1e-5f);
    r = r * (1.5f - 0.5f * (var + 1e-5f) * r * r);   // Newton refine
    float4 wv = ((const float4*)w)[lane];
    float4 bv = ((const float4*)b)[lane];
    float4 o4;
    o4.x = dx * r * wv.x + bv.x;
    o4.y = dy * r * wv.y + bv.y;
    o4.z = dz * r * wv.z + bv.z;
    o4.w = dw * r * wv.w + bv.w;
    ((float4*)(g_x1 + (size_t)warp * Cc))[lane] = o4;
}

// -------------------- fp32 SGEMM tile (R11, passed) ------------------------
__device__ __forceinline__ void gemm_tile(const float* __restrict__ A,
                                          const float* __restrict__ W,
                                          const float* __restrict__ bias,
                                          float* __restrict__ Y,
                                          int M, int act, int bm) {
    __shared__ float As[16][132];
    __shared__ float Bs[16][132];
    int tid = threadIdx.x;
    int ty = tid >> 4, tx = tid & 15;

    unsigned long long acc2[8][4];
    #pragma unroll
    for (int i = 0; i < 8; i++)
        #pragma unroll
        for (int j = 0; j < 4; j++) acc2[i][j] = 0ull;

    for (int k0 = 0; k0 < 128; k0 += 16) {
        #pragma unroll
        for (int u = 0; u < 2; u++) {
            int q = tid + u * 256;
            int row = q >> 2, c4 = q & 3;
            int grow = bm + row;
            float4 a = (grow < M)
                ? ((const float4*)(A + (size_t)grow * 128 + k0))[c4]
                : make_float4(0.f, 0.f, 0.f, 0.f);
            As[c4*4+0][row] = a.x;
            As[c4*4+1][row] = a.y;
            As[c4*4+2][row] = a.z;
            As[c4*4+3][row] = a.w;
        }
        #pragma unroll
        for (int u = 0; u < 2; u++) {
            int q = tid + u * 256;
            int row = q >> 5, c4 = q & 31;
            float4 bvec = ((const float4*)(W + (size_t)(k0 + row) * 128))[c4];
            *(float4*)&Bs[row][c4 * 4] = bvec;
        }
        __syncthreads();
        #pragma unroll
        for (int k = 0; k < 16; k++) {
            float a[8], bb[8];
            *(float4*)&a[0]  = *(const float4*)&As[k][ty * 8];
            *(float4*)&a[4]  = *(const float4*)&As[k][ty * 8 + 4];
            *(float4*)&bb[0] = *(const float4*)&Bs[k][tx * 8];
            *(float4*)&bb[4] = *(const float4*)&Bs[k][tx * 8 + 4];
            unsigned long long b0 = pk64(bb[0], bb[1]);
            unsigned long long b1 = pk64(bb[2], bb[3]);
            unsigned long long b2 = pk64(bb[4], bb[5]);
            unsigned long long b3 = pk64(bb[6], bb[7]);
            #pragma unroll
            for (int i = 0; i < 8; i++) {
                unsigned long long aa = pk64(a[i], a[i]);
                acc2[i][0] = ffma2(aa, b0, acc2[i][0]);
                acc2[i][1] = ffma2(aa, b1, acc2[i][1]);
                acc2[i][2] = ffma2(aa, b2, acc2[i][2]);
                acc2[i][3] = ffma2(aa, b3, acc2[i][3]);
            }
        }
        __syncthreads();
    }

    float bset[8];
    *(float4*)&bset[0] = *(const float4*)(bias + tx * 8);
    *(float4*)&bset[4] = *(const float4*)(bias + tx * 8 + 4);
    #pragma unroll
    for (int i = 0; i < 8; i++) {
        int grow = bm + ty * 8 + i;
        if (grow >= M) continue;
        float o[8];
        #pragma unroll
        for (int j = 0; j < 4; j++) {
            float v0 = lo32(acc2[i][j]) + bset[2*j];
            float v1 = hi32(acc2[i][j]) + bset[2*j + 1];
            if (act) {
                v0 = 0.5f * v0 * (1.0f + erff(v0 * 0.70710678118654752f));
                v1 = 0.5f * v1 * (1.0f + erff(v1 * 0.70710678118654752f));
            }
            o[2*j]     = v0;
            o[2*j + 1] = v1;
        }
        *(float4*)(Y + (size_t)grow * 128 + tx * 8)     = *(float4*)&o[0];
        *(float4*)(Y + (size_t)grow * 128 + tx * 8 + 4) = *(float4*)&o[4];
    }
}

// Same tile, epilogue packs to fp16 pairs (XL/XR planes).
__device__ __forceinline__ void gemm_tile_h(const float* __restrict__ A,
                                            const float* __restrict__ W,
                                            const float* __restrict__ bias,
                                            unsigned* __restrict__ Y16,
                                            int M, int bm) {
    __shared__ float As[16][132];
    __shared__ float Bs[16][132];
    int tid = threadIdx.x;
    int ty = tid >> 4, tx = tid & 15;

    unsigned long long acc2[8][4];
    #pragma unroll
    for (int i = 0; i < 8; i++)
        #pragma unroll
        for (int j = 0; j < 4; j++) acc2[i][j] = 0ull;

    for (int k0 = 0; k0 < 128; k0 += 16) {
        #pragma unroll
        for (int u = 0; u < 2; u++) {
            int q = tid + u * 256;
            int row = q >> 2, c4 = q & 3;
            int grow = bm + row;
            float4 a = (grow < M)
                ? ((const float4*)(A + (size_t)grow * 128 + k0))[c4]
                : make_float4(0.f, 0.f, 0.f, 0.f);
            As[c4*4+0][row] = a.x;
            As[c4*4+1][row] = a.y;
            As[c4*4+2][row] = a.z;
            As[c4*4+3][row] = a.w;
        }
        #pragma unroll
        for (int u = 0; u < 2; u++) {
            int q = tid + u * 256;
            int row = q >> 5, c4 = q & 31;
            float4 bvec = ((const float4*)(W + (size_t)(k0 + row) * 128))[c4];
            *(float4*)&Bs[row][c4 * 4] = bvec;
        }
        __syncthreads();
        #pragma unroll
        for (int k = 0; k < 16; k++) {
            float a[8], bb[8];
            *(float4*)&a[0]  = *(const float4*)&As[k][ty * 8];
            *(float4*)&a[4]  = *(const float4*)&As[k][ty * 8 + 4];
            *(float4*)&bb[0] = *(const float4*)&Bs[k][tx * 8];
            *(float4*)&bb[4] = *(const float4*)&Bs[k][tx * 8 + 4];
            unsigned long long b0 = pk64(bb[0], bb[1]);
            unsigned long long b1 = pk64(bb[2], bb[3]);
            unsigned long long b2 = pk64(bb[4], bb[5]);
            unsigned long long b3 = pk64(bb[6], bb[7]);
            #pragma unroll
            for (int i = 0; i < 8; i++) {
                unsigned long long aa = pk64(a[i], a[i]);
                acc2[i][0] = ffma2(aa, b0, acc2[i][0]);
                acc2[i][1] = ffma2(aa, b1, acc2[i][1]);
                acc2[i][2] = ffma2(aa, b2, acc2[i][2]);
                acc2[i][3] = ffma2(aa, b3, acc2[i][3]);
            }
        }
        __syncthreads();
    }

    float bset[8];
    *(float4*)&bset[0] = *(const float4*)(bias + tx * 8);
    *(float4*)&bset[4] = *(const float4*)(bias + tx * 8 + 4);
    #pragma unroll
    for (int i = 0; i < 8; i++) {
        int grow = bm + ty * 8 + i;
        if (grow >= M) continue;
        uint4 pk;
        pk.x = hpack2(lo32(acc2[i][0]) + bset[0], hi32(acc2[i][0]) + bset[1]);
        pk.y = hpack2(lo32(acc2[i][1]) + bset[2], hi32(acc2[i][1]) + bset[3]);
        pk.z = hpack2(lo32(acc2[i][2]) + bset[4], hi32(acc2[i][2]) + bset[5]);
        pk.w = hpack2(lo32(acc2[i][3]) + bset[6], hi32(acc2[i][3]) + bset[7]);
        ((uint4*)(Y16 + (size_t)grow * 64))[tx] = pk;
    }
}

// 6-way GEMM: XL[r] = x1@Wl[r]+bl[r],  XR[r] = x1@Wr[r]+br[r]  (fp16 planes)
__global__ void __launch_bounds__(256) gemm6_kernel(const float* __restrict__ Wl,
                                                    const float* __restrict__ bl,
                                                    const float* __restrict__ Wr,
                                                    const float* __restrict__ br) {
    int y = blockIdx.y;
    int r = (y < 3) ? y : y - 3;
    const float* W  = ((y < 3) ? Wl : Wr) + (size_t)r * CC;
    const float* bb = ((y < 3) ? bl : br) + (size_t)r * Cc;
    unsigned* Y = ((y < 3) ? g_XLp : g_XRp) + (size_t)r * NCH;
    gemm_tile_h(g_x1, W, bb, Y, Nn, blockIdx.x * 128);
}

__global__ void __launch_bounds__(256) mlp1_kernel(const float* __restrict__ W,
                                                   const float* __restrict__ b) {
    gemm_tile(g_x1, W, b, g_h, Nn, 1, blockIdx.x * 128);
}

__global__ void __launch_bounds__(256) mlp2_kernel(const float* __restrict__ W,
                                                   const float* __restrict__ b) {
    gemm_tile(g_h, W, b, g_mlp, Nn, 1, blockIdx.x * 128);
}

// -------------------- Edge pass 1: logits -> exp -> denominators -----------
__global__ void e1_kernel(const float* __restrict__ att) {
    int gw = (blockIdx.x * blockDim.x + threadIdx.x) >> 5;
    int lane = threadIdx.x & 31;
    if (gw >= Ee) return;
    int s = g_src[gw], d = g_dst[gw], t = g_et[gw];
    const uint2* xl = (const uint2*)(g_XLp + (size_t)t * NCH + (size_t)s * 64);
    const uint2* xr = (const uint2*)(g_XRp + (size_t)t * NCH + (size_t)d * 64);
    uint2 ua = xl[lane];
    uint2 ub = xr[lane];
    float z0 = hlo(ua.x) + hlo(ub.x);
    float z1 = hhi(ua.x) + hhi(ub.x);
    float z2 = hlo(ua.y) + hlo(ub.y);
    float z3 = hhi(ua.y) + hhi(ub.y);
    z0 = (z0 >= 0.f) ? z0 : 0.2f * z0;
    z1 = (z1 >= 0.f) ? z1 : 0.2f * z1;
    z2 = (z2 >= 0.f) ? z2 : 0.2f * z2;
    z3 = (z3 >= 0.f) ? z3 : 0.2f * z3;
    float4 av = ((const float4*)(att + (size_t)t * Cc))[lane];
    float e = z0 * av.x + z1 * av.y + z2 * av.z + z3 * av.w;
    e += __shfl_xor_sync(0xffffffffu, e, 1);
    e += __shfl_xor_sync(0xffffffffu, e, 2);
    e += __shfl_xor_sync(0xffffffffu, e, 4);     // 8-lane group = one head
    if ((lane & 7) == 0) {
        int h = lane >> 3;
        float p = expf(e);
        g_p[(size_t)gw * 4 + h] = p;
        atomicAdd(&g_den[(size_t)d * 12 + t * 4 + h], p);
    }
}

// -------------------- Edge pass 2: alpha * xl[src] scatter -----------------
__global__ void e2_kernel() {
    int gw = (blockIdx.x * blockDim.x + threadIdx.x) >> 5;
    int lane = threadIdx.x & 31;
    if (gw >= Ee) return;
    int s = g_src[gw], d = g_dst[gw], t = g_et[gw];
    int h = lane >> 3;
    float p   = g_p[(size_t)gw * 4 + h];
    float den = g_den[(size_t)d * 12 + t * 4 + h];
    float alpha = p / ((den > 0.f) ? den : 1.f);
    const uint2* xl = (const uint2*)(g_XLp + (size_t)t * NCH + (size_t)s * 64);
    uint2 ua = xl[lane];
    float a0 = hlo(ua.x), a1 = hhi(ua.x), a2 = hlo(ua.y), a3 = hhi(ua.y);
    float* dst = g_gat + (size_t)d * Cc + lane * 4;
    asm volatile("red.global.add.v4.f32 [%0], {%1, %2, %3, %4};"
                 :: "l"(dst), "f"(a0 * alpha), "f"(a1 * alpha),
                    "f"(a2 * alpha), "f"(a3 * alpha)
                 : "memory");
}

// -------------------- final residual ---------------------------------------
__global__ void final_kernel(const float* __restrict__ x,
                             const float* __restrict__ gbias,
                             float* __restrict__ out) {
    int i = blockIdx.x * blockDim.x + threadIdx.x;
    if (i >= NC) return;
    int c = i & 127;
    float gb = gbias[c] + gbias[128 + c] + gbias[256 + c];
    out[i] = x[i] + g_gat[i] + g_mlp[i] + gb;
}

// ---------------------------------------------------------------------------
extern "C" void kernel_launch(void* const* d_in, const int* in_sizes, int n_in,
                              void* d_out, int out_size) {
    const float* x    = (const float*)d_in[0];
    const void*  ei   = d_in[1];                  // int64 or int32, detected on-device
    const int*   ea   = (const int*)d_in[2];
    const float* ln_w = (const float*)d_in[3];
    const float* ln_b = (const float*)d_in[4];
    const float* Wl   = (const float*)d_in[5];
    const float* bl   = (const float*)d_in[6];
    const float* Wr   = (const float*)d_in[7];
    const float* br   = (const float*)d_in[8];
    const float* att  = (const float*)d_in[9];
    const float* gb   = (const float*)d_in[10];
    const float* mW1  = (const float*)d_in[11];
    const float* mb1  = (const float*)d_in[12];
    const float* mW2  = (const float*)d_in[13];
    const float* mb2  = (const float*)d_in[14];
    float* out = (float*)d_out;

    // Fork/join side stream for the MLP chain (host-object creation; happens
    // only on real invocations — graph replays re-execute captured nodes, not
    // this host code). Events express the cross-stream dependencies; no syncs.
    cudaStream_t s2;
    cudaEvent_t evF, evJ;
    cudaStreamCreateWithFlags(&s2, cudaStreamNonBlocking);
    cudaEventCreateWithFlags(&evF, cudaEventDisableTiming);
    cudaEventCreateWithFlags(&evJ, cudaEventDisableTiming);

    detect_kernel<<<1, 1>>>(ei);
    convert_kernel<<<(Ee + 255) / 256, 256>>>(ei, ea);
    zero_kernel<<<(NC + 255) / 256, 256>>>();
    ln_kernel<<<(Nn * 32 + 255) / 256, 256>>>(x, ln_w, ln_b);

    // Fork: MLP chain depends only on g_x1 (ln output).
    cudaEventRecord(evF, 0);
    cudaStreamWaitEvent(s2, evF, 0);

    const int MT = (Nn + 127) / 128;  // 782 row tiles
    // null stream: relation GEMMs then edge passes
    gemm6_kernel<<<dim3(MT, 6), 256>>>(Wl, bl, Wr, br);
    e1_kernel<<<(Ee * 32) / 256, 256>>>(att);
    e2_kernel<<<(Ee * 32) / 256, 256>>>();

    // side stream: MLP chain
    mlp1_kernel<<<MT, 256, 0, s2>>>(mW1, mb1);
    mlp2_kernel<<<MT, 256, 0, s2>>>(mW2, mb2);
    cudaEventRecord(evJ, s2);

    // Join: final needs g_gat (e2, null stream) and g_mlp (mlp2, s2).
    cudaStreamWaitEvent(0, evJ, 0);
    final_kernel<<<(NC + 255) / 256, 256>>>(x, gb, out);

    // Release host objects (not device memory; not captured operations).
    cudaEventDestroy(evF);
    cudaEventDestroy(evJ);
    cudaStreamDestroy(s2);
}